// round 1
// baseline (speedup 1.0000x reference)
#include <cuda_runtime.h>

#define B_ 16
#define N_ 196
#define C_ 768
#define H_ 512
#define O_ 128

// Scratch: colsum[z][b][h], fully overwritten each launch (no zeroing needed,
// each element written by exactly one block). __device__ global per alloc rules.
__device__ float g_colsum[2 * B_ * H_];

// GEMM + ReLU + column-sum fused.
// Block = (h_tile of 64, batch b, input z). Loops all 196 rows internally.
// 256 threads, each computes a 4x4 microtile; BK=32 K-chunks staged in SMEM.
__global__ __launch_bounds__(256) void gemm_relu_colsum(
    const float* __restrict__ x1, const float* __restrict__ x2,
    const float* __restrict__ W1, const float* __restrict__ W2)
{
    const int z  = blockIdx.z;
    const float* __restrict__ x = z ? x2 : x1;
    const float* __restrict__ W = z ? W2 : W1;
    const int b  = blockIdx.y;
    const int gh = blockIdx.x * 64;

    __shared__ float As[64][36];   // x tile [m][k], padded row (36*4=144B, 16B-aligned)
    __shared__ float Bs[32][64];   // W tile [k][n]
    __shared__ float red[16][64];  // column reduction

    const int tid = threadIdx.x;
    const int ty = tid >> 4;   // 0..15 -> row group
    const int tx = tid & 15;   // 0..15 -> col group

    float colpart[4] = {0.f, 0.f, 0.f, 0.f};

    for (int mbase = 0; mbase < N_; mbase += 64) {
        float acc[4][4];
        #pragma unroll
        for (int r = 0; r < 4; r++)
            #pragma unroll
            for (int c = 0; c < 4; c++) acc[r][c] = 0.f;

        for (int kbase = 0; kbase < C_; kbase += 32) {
            // ---- load x tile: 64 rows x 32 k (8 floats = 2 float4 per thread)
            {
                int m  = tid >> 2;          // 0..63
                int kq = (tid & 3) * 4;     // 0,4,8,12
                int gm = mbase + m;
                float4 v0 = make_float4(0.f, 0.f, 0.f, 0.f);
                float4 v1 = v0;
                if (gm < N_) {
                    const float* src = x + ((size_t)b * N_ + gm) * C_ + kbase;
                    v0 = *(const float4*)(src + kq);
                    v1 = *(const float4*)(src + kq + 16);
                }
                *(float4*)&As[m][kq]      = v0;
                *(float4*)&As[m][kq + 16] = v1;
            }
            // ---- load W tile: 32 k x 64 n (2 float4 per thread)
            {
                int k  = tid >> 4;          // 0..15
                int nq = (tid & 15) * 4;    // 0..60
                const float* src = W + (size_t)(kbase + k) * H_ + gh + nq;
                *(float4*)&Bs[k][nq]      = *(const float4*)src;
                *(float4*)&Bs[k + 16][nq] = *(const float4*)(src + 16 * H_);
            }
            __syncthreads();

            #pragma unroll
            for (int k = 0; k < 32; k++) {
                float4 bv = *(const float4*)&Bs[k][tx * 4];
                float a0 = As[ty * 4 + 0][k];
                float a1 = As[ty * 4 + 1][k];
                float a2 = As[ty * 4 + 2][k];
                float a3 = As[ty * 4 + 3][k];
                acc[0][0] += a0 * bv.x; acc[0][1] += a0 * bv.y; acc[0][2] += a0 * bv.z; acc[0][3] += a0 * bv.w;
                acc[1][0] += a1 * bv.x; acc[1][1] += a1 * bv.y; acc[1][2] += a1 * bv.z; acc[1][3] += a1 * bv.w;
                acc[2][0] += a2 * bv.x; acc[2][1] += a2 * bv.y; acc[2][2] += a2 * bv.z; acc[2][3] += a2 * bv.w;
                acc[3][0] += a3 * bv.x; acc[3][1] += a3 * bv.y; acc[3][2] += a3 * bv.z; acc[3][3] += a3 * bv.w;
            }
            __syncthreads();
        }

        // ReLU + accumulate into per-thread column partials.
        // Rows beyond N_ have acc == 0 exactly (zero-filled loads), relu(0)=0.
        #pragma unroll
        for (int r = 0; r < 4; r++)
            #pragma unroll
            for (int c = 0; c < 4; c++)
                colpart[c] += fmaxf(acc[r][c], 0.f);
    }

    // Reduce the 16 row-groups per column.
    #pragma unroll
    for (int c = 0; c < 4; c++) red[ty][tx * 4 + c] = colpart[c];
    __syncthreads();
    if (tid < 64) {
        float s = 0.f;
        #pragma unroll
        for (int j = 0; j < 16; j++) s += red[j][tid];
        g_colsum[(size_t)z * (B_ * H_) + b * H_ + gh + tid] = s;
    }
}

// out[b,o] = sum_h c1[b,h]*c2[b,h]*Wp[h,o] + bp[o]*N*N
__global__ void finalize_kernel(const float* __restrict__ Wp,
                                const float* __restrict__ bp,
                                float* __restrict__ out)
{
    const int b = blockIdx.x;
    const int o = threadIdx.x;
    const float* __restrict__ c1 = g_colsum + b * H_;
    const float* __restrict__ c2 = g_colsum + B_ * H_ + b * H_;
    float s = 0.f;
    #pragma unroll 8
    for (int h = 0; h < H_; h++)
        s += c1[h] * c2[h] * Wp[h * O_ + o];
    out[b * O_ + o] = s + bp[o] * (float)(N_ * N_);
}

extern "C" void kernel_launch(void* const* d_in, const int* in_sizes, int n_in,
                              void* d_out, int out_size)
{
    const float* x1 = (const float*)d_in[0];
    const float* x2 = (const float*)d_in[1];
    const float* W1 = (const float*)d_in[2];
    const float* W2 = (const float*)d_in[3];
    const float* Wp = (const float*)d_in[4];
    const float* bp = (const float*)d_in[5];
    float* out = (float*)d_out;

    dim3 grid(H_ / 64, B_, 2);
    gemm_relu_colsum<<<grid, 256>>>(x1, x2, W1, W2);
    finalize_kernel<<<B_, O_>>>(Wp, bp, out);
}

// round 3
// speedup vs baseline: 2.4786x; 2.4786x over previous
#include <cuda_runtime.h>
#include <cuda_bf16.h>
#include <cstdint>

#define B_ 16
#define N_ 196
#define C_ 768
#define H_ 512
#define O_ 128

// ---------------- device scratch (static, no allocs) ----------------
// A panels: [z][b][row 0..255][k 0..767] bf16, rows >= 196 are zero
__device__ __align__(256) __nv_bfloat16 g_Ahi[2u*16*256*768];
__device__ __align__(256) __nv_bfloat16 g_Alo[2u*16*256*768];
// B panels (W transposed): [z][h 0..511][k 0..767] bf16
__device__ __align__(256) __nv_bfloat16 g_Bhi[2u*512*768];
__device__ __align__(256) __nv_bfloat16 g_Blo[2u*512*768];
// partial column sums: [z][b][mt 4][h 512]
__device__ float g_part[2*16*4*512];

// ---------------- helpers ----------------
__device__ __forceinline__ uint32_t smem_u32(const void* p) {
    uint32_t a;
    asm("{ .reg .u64 t; cvta.to.shared.u64 t, %1; cvt.u32.u64 %0, t; }" : "=r"(a) : "l"(p));
    return a;
}
__device__ __forceinline__ void cp16(uint32_t dst, const void* src) {
    asm volatile("cp.async.cg.shared.global [%0], [%1], 16;" :: "r"(dst), "l"(src) : "memory");
}
__device__ __forceinline__ void ldsm_x4(uint32_t* r, uint32_t addr) {
    asm volatile("ldmatrix.sync.aligned.m8n8.x4.shared.b16 {%0,%1,%2,%3}, [%4];"
                 : "=r"(r[0]), "=r"(r[1]), "=r"(r[2]), "=r"(r[3]) : "r"(addr));
}
__device__ __forceinline__ void mma_bf16(float* d, const uint32_t* a, const uint32_t* b) {
    asm volatile("mma.sync.aligned.m16n8k16.row.col.f32.bf16.bf16.f32 "
                 "{%0,%1,%2,%3}, {%4,%5,%6,%7}, {%8,%9}, {%0,%1,%2,%3};"
                 : "+f"(d[0]), "+f"(d[1]), "+f"(d[2]), "+f"(d[3])
                 : "r"(a[0]), "r"(a[1]), "r"(a[2]), "r"(a[3]), "r"(b[0]), "r"(b[1]));
}
__device__ __forceinline__ uint32_t bf2_bits(float a, float b) {
    __nv_bfloat162 t = __floats2bfloat162_rn(a, b);
    return *reinterpret_cast<uint32_t*>(&t);
}

// ---------------- pack A: x fp32 -> hi/lo bf16 row-major panels ----------------
__global__ void pack_A(const float* __restrict__ x1, const float* __restrict__ x2) {
    int u = blockIdx.x * blockDim.x + threadIdx.x;   // 786432 total
    int kg = u % 96;  int t = u / 96;
    int row = t & 255; t >>= 8;
    int b = t & 15;    t >>= 4;
    int z = t;
    const float* x = z ? x2 : x1;
    float f[8];
    if (row < N_) {
        const float4* src = reinterpret_cast<const float4*>(x + ((size_t)b * N_ + row) * C_ + kg * 8);
        float4 v0 = src[0], v1 = src[1];
        f[0]=v0.x; f[1]=v0.y; f[2]=v0.z; f[3]=v0.w;
        f[4]=v1.x; f[5]=v1.y; f[6]=v1.z; f[7]=v1.w;
    } else {
        #pragma unroll
        for (int i = 0; i < 8; i++) f[i] = 0.f;
    }
    uint32_t hi[4], lo[4];
    #pragma unroll
    for (int i = 0; i < 4; i++) {
        float a = f[2*i], bb = f[2*i+1];
        __nv_bfloat162 h2 = __floats2bfloat162_rn(a, bb);
        hi[i] = *reinterpret_cast<uint32_t*>(&h2);
        lo[i] = bf2_bits(a - __bfloat162float(h2.x), bb - __bfloat162float(h2.y));
    }
    size_t off = ((size_t)(z * 16 + b) * 256 + row) * 768 + kg * 8;
    *reinterpret_cast<uint4*>(g_Ahi + off) = make_uint4(hi[0], hi[1], hi[2], hi[3]);
    *reinterpret_cast<uint4*>(g_Alo + off) = make_uint4(lo[0], lo[1], lo[2], lo[3]);
}

// ---------------- pack B: W [C,H] fp32 -> transposed hi/lo bf16 [H,C] ----------------
__global__ void pack_B(const float* __restrict__ W1, const float* __restrict__ W2) {
    int kc = blockIdx.x, hb = blockIdx.y, z = blockIdx.z;
    const float* W = z ? W2 : W1;
    __shared__ float ts[64][65];
    int tid = threadIdx.x;
    int c0 = kc * 64, h0 = hb * 64;
    #pragma unroll
    for (int i = 0; i < 16; i++) {
        int idx = tid + i * 256;
        int cl = idx >> 6, hl = idx & 63;
        ts[cl][hl] = W[(size_t)(c0 + cl) * H_ + h0 + hl];
    }
    __syncthreads();
    #pragma unroll
    for (int j = 0; j < 2; j++) {
        int unit = tid + j * 256;          // 512 units: 64 h-rows x 8 kgroups
        int row = unit >> 3, kg = unit & 7;
        float f[8];
        #pragma unroll
        for (int i = 0; i < 8; i++) f[i] = ts[kg * 8 + i][row];
        uint32_t hi[4], lo[4];
        #pragma unroll
        for (int i = 0; i < 4; i++) {
            float a = f[2*i], bb = f[2*i+1];
            __nv_bfloat162 h2 = __floats2bfloat162_rn(a, bb);
            hi[i] = *reinterpret_cast<uint32_t*>(&h2);
            lo[i] = bf2_bits(a - __bfloat162float(h2.x), bb - __bfloat162float(h2.y));
        }
        size_t off = ((size_t)z * 512 + h0 + row) * 768 + c0 + kg * 8;
        *reinterpret_cast<uint4*>(g_Bhi + off) = make_uint4(hi[0], hi[1], hi[2], hi[3]);
        *reinterpret_cast<uint4*>(g_Blo + off) = make_uint4(lo[0], lo[1], lo[2], lo[3]);
    }
}

// ---------------- GEMM: mma.sync bf16 3-term split + relu + colsum ----------------
// Block tile: M=64, N=256, BK=32, 256 threads (8 warps: wm in {0,1}, wn in {0..3},
// warp tile m32 x n64). Smem: 2 stages x (A hi/lo 64x32 + B hi/lo 256x32),
// rows padded to 80B for conflict-free ldmatrix.
#define STAGE_BYTES 51200
#define A_TERM 5120
#define B_OFF 10240
#define B_TERM 20480
#define SMEM_TOTAL (2*STAGE_BYTES)

__device__ __forceinline__ void load_stage(
    uint32_t sbase, int buf, int kbase, int tid,
    const __nv_bfloat16* Ah, const __nv_bfloat16* Al,
    const __nv_bfloat16* Bh, const __nv_bfloat16* Bl)
{
    uint32_t base = sbase + buf * STAGE_BYTES;
    #pragma unroll
    for (int i = 0; i < 2; i++) {                 // A: 512 16B units
        int u = tid + i * 256;
        int term = u & 1, q = (u >> 1) & 3, row = u >> 3;
        const __nv_bfloat16* src = (term ? Al : Ah) + (size_t)row * 768 + kbase + q * 8;
        cp16(base + term * A_TERM + row * 80 + q * 16, src);
    }
    #pragma unroll
    for (int i = 0; i < 8; i++) {                 // B: 2048 16B units
        int u = tid + i * 256;
        int term = u & 1, q = (u >> 1) & 3, row = u >> 3;
        const __nv_bfloat16* src = (term ? Bl : Bh) + (size_t)row * 768 + kbase + q * 8;
        cp16(base + B_OFF + term * B_TERM + row * 80 + q * 16, src);
    }
    asm volatile("cp.async.commit_group;" ::: "memory");
}

__global__ __launch_bounds__(256, 1) void gemm_hmma() {
    extern __shared__ char sm[];
    uint32_t sb = smem_u32(sm);
    int tid = threadIdx.x, wid = tid >> 5, lane = tid & 31;
    int z = blockIdx.z, b = blockIdx.y;
    int mt = blockIdx.x >> 1, nt = blockIdx.x & 1;
    int wm = wid & 1, wn = wid >> 1;

    const __nv_bfloat16* Ah = g_Ahi + ((size_t)(z * 16 + b) * 256 + mt * 64) * 768;
    const __nv_bfloat16* Al = g_Alo + ((size_t)(z * 16 + b) * 256 + mt * 64) * 768;
    const __nv_bfloat16* Bh = g_Bhi + ((size_t)z * 512 + nt * 256) * 768;
    const __nv_bfloat16* Bl = g_Blo + ((size_t)z * 512 + nt * 256) * 768;

    float acc[2][8][4];
    #pragma unroll
    for (int mf = 0; mf < 2; mf++)
        #pragma unroll
        for (int nf = 0; nf < 8; nf++)
            #pragma unroll
            for (int d = 0; d < 4; d++) acc[mf][nf][d] = 0.f;

    // per-lane ldmatrix row/unit offsets (bytes within a term region)
    // A: row = wm*32 + mf*16 + (lane&7) + ((lane>>3)&1)*8 ; unit = lane>>4
    uint32_t aoff[2];
    #pragma unroll
    for (int mf = 0; mf < 2; mf++) {
        int row = wm * 32 + mf * 16 + (lane & 7) + ((lane >> 3) & 1) * 8;
        aoff[mf] = row * 80 + (lane >> 4) * 16;
    }
    // B: row = wn*64 + np*16 + (lane&7) + (lane>>4)*8 ; unit = (lane>>3)&1
    uint32_t boff[4];
    #pragma unroll
    for (int np = 0; np < 4; np++) {
        int row = wn * 64 + np * 16 + (lane & 7) + (lane >> 4) * 8;
        boff[np] = row * 80 + ((lane >> 3) & 1) * 16;
    }

    load_stage(sb, 0, 0, tid, Ah, Al, Bh, Bl);

    for (int s = 0; s < 24; s++) {
        if (s < 23) {
            load_stage(sb, (s + 1) & 1, (s + 1) * 32, tid, Ah, Al, Bh, Bl);
            asm volatile("cp.async.wait_group 1;" ::: "memory");
        } else {
            asm volatile("cp.async.wait_group 0;" ::: "memory");
        }
        __syncthreads();

        uint32_t abase = sb + (s & 1) * STAGE_BYTES;
        uint32_t bbase = abase + B_OFF;
        #pragma unroll
        for (int kk = 0; kk < 2; kk++) {
            uint32_t a[2][2][4];     // [term][mf]
            uint32_t bf[2][4][4];    // [term][np] -> frags nf=2np(r0,r1), 2np+1(r2,r3)
            #pragma unroll
            for (int t = 0; t < 2; t++)
                #pragma unroll
                for (int mf = 0; mf < 2; mf++)
                    ldsm_x4(a[t][mf], abase + t * A_TERM + aoff[mf] + kk * 32);
            #pragma unroll
            for (int t = 0; t < 2; t++)
                #pragma unroll
                for (int np = 0; np < 4; np++)
                    ldsm_x4(bf[t][np], bbase + t * B_TERM + boff[np] + kk * 32);
            #pragma unroll
            for (int mf = 0; mf < 2; mf++)
                #pragma unroll
                for (int nf = 0; nf < 8; nf++) {
                    int np = nf >> 1, hh = (nf & 1) * 2;
                    uint32_t bh[2] = { bf[0][np][hh], bf[0][np][hh + 1] };
                    uint32_t bl[2] = { bf[1][np][hh], bf[1][np][hh + 1] };
                    mma_bf16(acc[mf][nf], a[0][mf], bh);   // hi*hi
                    mma_bf16(acc[mf][nf], a[0][mf], bl);   // hi*lo
                    mma_bf16(acc[mf][nf], a[1][mf], bh);   // lo*hi
                }
        }
        __syncthreads();
    }

    // ---------------- epilogue: relu + column sums ----------------
    // D frag: d0,d1 = (row=lane/4, col=2(lane%4)+{0,1}); d2,d3 = row+8.
    float* red = (float*)sm;     // [2][256] floats, reuse smem buf0
    #pragma unroll
    for (int nf = 0; nf < 8; nf++) {
        float s0 = 0.f, s1 = 0.f;
        #pragma unroll
        for (int mf = 0; mf < 2; mf++) {
            s0 += fmaxf(acc[mf][nf][0], 0.f) + fmaxf(acc[mf][nf][2], 0.f);
            s1 += fmaxf(acc[mf][nf][1], 0.f) + fmaxf(acc[mf][nf][3], 0.f);
        }
        #pragma unroll
        for (int off = 4; off < 32; off <<= 1) {
            s0 += __shfl_xor_sync(0xffffffff, s0, off);
            s1 += __shfl_xor_sync(0xffffffff, s1, off);
        }
        if (lane < 4) {
            red[wm * 256 + wn * 64 + nf * 8 + lane * 2]     = s0;
            red[wm * 256 + wn * 64 + nf * 8 + lane * 2 + 1] = s1;
        }
    }
    __syncthreads();
    float part = red[tid] + red[256 + tid];
    g_part[((size_t)(z * 16 + b) * 4 + mt) * 512 + nt * 256 + tid] = part;
}

// ---------------- finalize: colsum combine + bilinear + Wp GEMV ----------------
__global__ void finalize2(const float* __restrict__ Wp, const float* __restrict__ bp,
                          float* __restrict__ out) {
    int b = blockIdx.x;
    int tid = threadIdx.x;   // 512
    __shared__ float sp[512];
    __shared__ float racc[512];
    {
        int h = tid;
        float c1 = 0.f, c2 = 0.f;
        #pragma unroll
        for (int mt = 0; mt < 4; mt++) {
            c1 += g_part[((size_t)(0 * 16 + b) * 4 + mt) * 512 + h];
            c2 += g_part[((size_t)(1 * 16 + b) * 4 + mt) * 512 + h];
        }
        sp[h] = c1 * c2;
    }
    __syncthreads();
    int o = tid & 127, hp = tid >> 7;
    float acc = 0.f;
    #pragma unroll 16
    for (int i = 0; i < 128; i++) {
        int h = hp * 128 + i;
        acc = fmaf(sp[h], Wp[h * O_ + o], acc);
    }
    racc[tid] = acc;
    __syncthreads();
    if (tid < 128)
        out[b * O_ + tid] = racc[tid] + racc[128 + tid] + racc[256 + tid] + racc[384 + tid]
                            + bp[tid] * 38416.f;
}

// ---------------- launch ----------------
extern "C" void kernel_launch(void* const* d_in, const int* in_sizes, int n_in,
                              void* d_out, int out_size) {
    const float* x1 = (const float*)d_in[0];
    const float* x2 = (const float*)d_in[1];
    const float* W1 = (const float*)d_in[2];
    const float* W2 = (const float*)d_in[3];
    const float* Wp = (const float*)d_in[4];
    const float* bp = (const float*)d_in[5];
    float* out = (float*)d_out;

    cudaFuncSetAttribute(gemm_hmma, cudaFuncAttributeMaxDynamicSharedMemorySize, SMEM_TOTAL);

    pack_A<<<3072, 256>>>(x1, x2);
    pack_B<<<dim3(12, 8, 2), 256>>>(W1, W2);
    gemm_hmma<<<dim3(8, 16, 2), 256, SMEM_TOTAL>>>();
    finalize2<<<16, 512>>>(Wp, bp, out);
}